// round 5
// baseline (speedup 1.0000x reference)
#include <cuda_runtime.h>
#include <cuda_bf16.h>
#include <stdint.h>

// WeightedRuleLayer: out[r,d] = tanh( sum_p lv[idx[r,p], d] * w[r,p,d] )
// Canonical shapes: lv [200000,128] f32, w [250000,8,128] f32,
// idx [250000,8] int32-or-int64, out [250000,128] f32.
//
// Inputs are identified BY SIZE (largest = weights, smallest = indices) and the
// index dtype is detected on-device (JAX silently downgrades int64->int32 when
// x64 is disabled). All launches are graph-capturable and deterministic.

__device__ int g_idx_is32;

__global__ void reset_flag_kernel() { g_idx_is32 = 0; }

// Scan the first n64 int64 words of the index buffer. This byte range is valid
// under either dtype (n64 = idx_elems/2: == whole buffer if int32, first half
// if int64). Any value outside [0, n_src) proves the buffer is int32.
__global__ void detect_idx_kernel(const long long* __restrict__ idx64,
                                  long long n64, long long n_src)
{
    long long i = (long long)blockIdx.x * blockDim.x + threadIdx.x;
    const long long stride = (long long)gridDim.x * blockDim.x;
    int bad = 0;
    for (; i < n64; i += stride) {
        long long v = idx64[i];
        if (v < 0 || v >= n_src) { bad = 1; break; }
    }
    if (bad) atomicOr(&g_idx_is32, 1);
}

// Fast path: D=128, P=8. One warp per rule, float4 per lane (512B/row txn).
__global__ void __launch_bounds__(256)
wrl_kernel_d128p8(const float* __restrict__ lv,
                  const float* __restrict__ w,
                  const void*  __restrict__ idx_raw,
                  float* __restrict__ out,
                  int n_rules)
{
    const int warp_id = (blockIdx.x * blockDim.x + threadIdx.x) >> 5;
    const int lane    = threadIdx.x & 31;
    if (warp_id >= n_rules) return;

    const int is32 = g_idx_is32;   // uniform, L2-cached broadcast

    long long my_idx = 0;
    if (lane < 8) {
        if (is32)
            my_idx = (long long)((const int*)idx_raw)[(long long)warp_id * 8 + lane];
        else
            my_idx = ((const long long*)idx_raw)[(long long)warp_id * 8 + lane];
    }

    const float4* wrow =
        reinterpret_cast<const float4*>(w + (long long)warp_id * (8 * 128));

    float4 acc = make_float4(0.f, 0.f, 0.f, 0.f);

#pragma unroll
    for (int p = 0; p < 8; ++p) {
        long long ip = __shfl_sync(0xffffffffu, my_idx, p);
        // Gathered rows: the only reused data -> default caching (L1+L2).
        float4 g = __ldg(reinterpret_cast<const float4*>(lv + ip * 128) + lane);
        // Weights: read exactly once -> streaming (evict-first) to protect L2.
        float4 ww = __ldcs(wrow + p * 32 + lane);
        acc.x = fmaf(g.x, ww.x, acc.x);
        acc.y = fmaf(g.y, ww.y, acc.y);
        acc.z = fmaf(g.z, ww.z, acc.z);
        acc.w = fmaf(g.w, ww.w, acc.w);
    }

    acc.x = tanhf(acc.x);
    acc.y = tanhf(acc.y);
    acc.z = tanhf(acc.z);
    acc.w = tanhf(acc.w);

    __stcs(reinterpret_cast<float4*>(out + (long long)warp_id * 128) + lane, acc);
}

// Generic fallback for non-canonical shapes: one thread per (r, d).
__global__ void wrl_kernel_generic(const float* __restrict__ lv,
                                   const float* __restrict__ w,
                                   const void*  __restrict__ idx_raw,
                                   float* __restrict__ out,
                                   long long R, long long P, long long D)
{
    long long i = (long long)blockIdx.x * blockDim.x + threadIdx.x;
    const long long stride = (long long)gridDim.x * blockDim.x;
    const long long total = R * D;
    const int is32 = g_idx_is32;
    for (; i < total; i += stride) {
        const long long r = i / D;
        const long long d = i - r * D;
        float acc = 0.f;
        for (long long p = 0; p < P; ++p) {
            long long ip = is32
                ? (long long)((const int*)idx_raw)[r * P + p]
                : ((const long long*)idx_raw)[r * P + p];
            acc = fmaf(lv[ip * D + d], w[(r * P + p) * D + d], acc);
        }
        out[i] = tanhf(acc);
    }
}

extern "C" void kernel_launch(void* const* d_in, const int* in_sizes, int n_in,
                              void* d_out, int out_size)
{
    // Identify inputs by element count: weights = largest, indices = smallest.
    int wi = 0, ii = 0;
    for (int k = 1; k < n_in; ++k) {
        if (in_sizes[k] > in_sizes[wi]) wi = k;
        if (in_sizes[k] < in_sizes[ii]) ii = k;
    }
    int li = 0;
    for (int k = 0; k < n_in; ++k) if (k != wi && k != ii) { li = k; break; }

    const float* lv  = (const float*)d_in[li];
    const float* w   = (const float*)d_in[wi];
    const void*  idx = (const void*) d_in[ii];
    float*       out = (float*)d_out;

    const long long w_elems   = in_sizes[wi];
    const long long idx_elems = in_sizes[ii];
    const long long lv_elems  = in_sizes[li];

    const long long D     = w_elems / idx_elems;     // 128
    const long long R     = (long long)out_size / D; // 250000
    const long long P     = idx_elems / R;           // 8
    const long long n_src = lv_elems / D;            // 200000

    // 1) Reset dtype flag (determinism across graph replays).
    reset_flag_kernel<<<1, 1>>>();

    // 2) Detect index dtype: scan idx_elems/2 int64 words (safe either way).
    {
        const long long n64 = idx_elems / 2;
        int blocks = (int)((n64 + 255) / 256);
        if (blocks > 1184) blocks = 1184;  // ~8 blocks/SM grid-stride
        if (blocks < 1) blocks = 1;
        detect_idx_kernel<<<blocks, 256>>>((const long long*)idx, n64, n_src);
    }

    // 3) Main compute.
    if (D == 128 && P == 8) {
        const int threads = 256;               // 8 warps/block
        const int blocks  = (int)((R + 7) / 8);
        wrl_kernel_d128p8<<<blocks, threads>>>(lv, w, idx, out, (int)R);
    } else {
        const long long total = R * D;
        int blocks = (int)((total + 255) / 256);
        if (blocks > 4736) blocks = 4736;
        wrl_kernel_generic<<<blocks, 256>>>(lv, w, idx, out, R, P, D);
    }
}

// round 7
// speedup vs baseline: 1.0415x; 1.0415x over previous
#include <cuda_runtime.h>
#include <cuda_bf16.h>
#include <stdint.h>

// WeightedRuleLayer: out[r,d] = tanh( sum_p lv[idx[r,p], d] * w[r,p,d] )
// Canonical shapes: lv [200000,128] f32, w [250000,8,128] f32,
// idx [250000,8] int32-or-int64, out [250000,128] f32.
//
// Single-launch design. Index dtype is detected PER-WARP inside the main
// kernel: reading the buffer as int32 at [8r, 8r+8) is in-bounds under either
// dtype; under an int64 layout the odd int32 lanes are the high halves of the
// 64-bit words and are all zero (indices < 2^31). Odd-lane-nonzero => int32.

__global__ void __launch_bounds__(256)
wrl_kernel_d128p8(const float* __restrict__ lv,
                  const float* __restrict__ w,
                  const void*  __restrict__ idx_raw,
                  float* __restrict__ out,
                  int n_rules)
{
    const int warp_id = (blockIdx.x * blockDim.x + threadIdx.x) >> 5;
    const int lane    = threadIdx.x & 31;
    if (warp_id >= n_rules) return;

    const long long base = (long long)warp_id * 8;

    // Probe as int32 (always in-bounds under either dtype). Streamed: read-once.
    int v32 = 0;
    if (lane < 8)
        v32 = __ldcs((const int*)idx_raw + base + lane);

    // int64 layout => odd lanes are zero high-halves. Any nonzero odd lane
    // proves int32 layout.
    const unsigned odd_nz =
        __ballot_sync(0xffffffffu, (lane < 8) && (lane & 1) && (v32 != 0));

    long long my_idx;
    if (odd_nz) {
        my_idx = (long long)v32;                       // int32 layout
    } else {
        my_idx = 0;                                    // int64 layout
        if (lane < 8)
            my_idx = __ldcs((const long long*)idx_raw + base + lane);
    }

    const float4* wrow =
        reinterpret_cast<const float4*>(w + (long long)warp_id * (8 * 128));

    float4 acc = make_float4(0.f, 0.f, 0.f, 0.f);

#pragma unroll
    for (int p = 0; p < 8; ++p) {
        long long ip = __shfl_sync(0xffffffffu, my_idx, p);
        // Gathered rows: the only reused data -> default caching (L1+L2).
        float4 g = __ldg(reinterpret_cast<const float4*>(lv + ip * 128) + lane);
        // Weights: read exactly once -> streaming (evict-first) to protect L2.
        float4 ww = __ldcs(wrow + p * 32 + lane);
        acc.x = fmaf(g.x, ww.x, acc.x);
        acc.y = fmaf(g.y, ww.y, acc.y);
        acc.z = fmaf(g.z, ww.z, acc.z);
        acc.w = fmaf(g.w, ww.w, acc.w);
    }

    acc.x = tanhf(acc.x);
    acc.y = tanhf(acc.y);
    acc.z = tanhf(acc.z);
    acc.w = tanhf(acc.w);

    __stcs(reinterpret_cast<float4*>(out + (long long)warp_id * 128) + lane, acc);
}

// ───────────── generic fallback (non-canonical shapes only) ─────────────

__device__ int g_idx_is32;

__global__ void detect_idx_kernel(const long long* __restrict__ idx64,
                                  long long n64, long long n_src)
{
    // Block-local verdict; all blocks reach the same verdict (an int32 buffer
    // makes virtually every int64-word invalid), so the unconditional write
    // below is race-free in value and deterministic across graph replays.
    long long i = (long long)blockIdx.x * blockDim.x + threadIdx.x;
    const long long stride = (long long)gridDim.x * blockDim.x;
    int bad = 0;
    for (; i < n64; i += stride) {
        long long v = idx64[i];
        if (v < 0 || v >= n_src) { bad = 1; break; }
    }
    bad = __syncthreads_or(bad);
    if (threadIdx.x == 0) g_idx_is32 = bad;
}

__global__ void wrl_kernel_generic(const float* __restrict__ lv,
                                   const float* __restrict__ w,
                                   const void*  __restrict__ idx_raw,
                                   float* __restrict__ out,
                                   long long R, long long P, long long D)
{
    long long i = (long long)blockIdx.x * blockDim.x + threadIdx.x;
    const long long stride = (long long)gridDim.x * blockDim.x;
    const long long total = R * D;
    const int is32 = g_idx_is32;
    for (; i < total; i += stride) {
        const long long r = i / D;
        const long long d = i - r * D;
        float acc = 0.f;
        for (long long p = 0; p < P; ++p) {
            long long ip = is32
                ? (long long)((const int*)idx_raw)[r * P + p]
                : ((const long long*)idx_raw)[r * P + p];
            acc = fmaf(lv[ip * D + d], w[(r * P + p) * D + d], acc);
        }
        out[i] = tanhf(acc);
    }
}

extern "C" void kernel_launch(void* const* d_in, const int* in_sizes, int n_in,
                              void* d_out, int out_size)
{
    // Identify inputs by element count: weights = largest, indices = smallest.
    int wi = 0, ii = 0;
    for (int k = 1; k < n_in; ++k) {
        if (in_sizes[k] > in_sizes[wi]) wi = k;
        if (in_sizes[k] < in_sizes[ii]) ii = k;
    }
    int li = 0;
    for (int k = 0; k < n_in; ++k) if (k != wi && k != ii) { li = k; break; }

    const float* lv  = (const float*)d_in[li];
    const float* w   = (const float*)d_in[wi];
    const void*  idx = (const void*) d_in[ii];
    float*       out = (float*)d_out;

    const long long w_elems   = in_sizes[wi];
    const long long idx_elems = in_sizes[ii];
    const long long lv_elems  = in_sizes[li];

    const long long D     = w_elems / idx_elems;     // 128
    const long long R     = (long long)out_size / D; // 250000
    const long long P     = idx_elems / R;           // 8
    const long long n_src = lv_elems / D;            // 200000

    if (D == 128 && P == 8) {
        // Single launch: dtype detection is per-warp inside the kernel.
        const int threads = 256;               // 8 warps/block
        const int blocks  = (int)((R + 7) / 8);
        wrl_kernel_d128p8<<<blocks, threads>>>(lv, w, idx, out, (int)R);
    } else {
        const long long n64 = idx_elems / 2;
        int dblocks = (int)((n64 + 255) / 256);
        if (dblocks > 1184) dblocks = 1184;
        if (dblocks < 1) dblocks = 1;
        detect_idx_kernel<<<dblocks, 256>>>((const long long*)idx, n64, n_src);

        const long long total = R * D;
        int blocks = (int)((total + 255) / 256);
        if (blocks > 4736) blocks = 4736;
        wrl_kernel_generic<<<blocks, 256>>>(lv, w, idx, out, R, P, D);
    }
}